// round 3
// baseline (speedup 1.0000x reference)
#include <cuda_runtime.h>

#define BB 256
#define TT 50
#define MM 20
#define EE 128
#define G3 384

// scratch (no cudaMalloc allowed); .bss -> zeroed at module load.
// Slots for t >= len are NEVER written, so they stay 0 forever (deterministic).
__device__ __align__(16) float g_ub[BB*TT*EE];   // basket means   (B,T,E)
__device__ __align__(16) float g_xg[BB*TT*G3];   // input gates    (B,T,3E)

typedef unsigned long long u64;

__device__ __forceinline__ void fma2(u64 &acc, u64 a, u64 b){
    asm("fma.rn.f32x2 %0, %1, %2, %0;" : "+l"(acc) : "l"(a), "l"(b));
}
__device__ __forceinline__ u64 add2(u64 a, u64 b){
    u64 r; asm("add.rn.f32x2 %0, %1, %2;" : "=l"(r) : "l"(a), "l"(b));
    return r;
}
__device__ __forceinline__ float hsum2(u64 v){
    float lo, hi;
    asm("mov.b64 {%0,%1}, %2;" : "=f"(lo), "=f"(hi) : "l"(v));
    return lo + hi;
}
__device__ __forceinline__ float sigf(float x){
    return __fdividef(1.f, 1.f + __expf(-x));
}
__device__ __forceinline__ float tanhfast(float x){
    return __fdividef(2.f, 1.f + __expf(-2.f*x)) - 1.f;
}

// ---------------------------------------------------------------------------
// K1: ub[b,t,:] = (1/basket) * sum_m emb[item_ids[b,t,m]]   (emb[0] == 0)
// One WARP per (b,t) row; lane covers one float4 chunk (32 lanes * 16B = 512B).
// ---------------------------------------------------------------------------
__global__ void __launch_bounds__(256) k_gather(const int* __restrict__ ids,
                                                const int* __restrict__ bsz,
                                                const int* __restrict__ lens,
                                                const float* __restrict__ emb){
    const int r = blockIdx.x * 8 + (threadIdx.x >> 5);
    const int lane = threadIdx.x & 31;
    const int b = r / TT;
    const int t = r - b*TT;
    if (t >= __ldg(lens + b)) return;             // uniform per warp

    const int4* ip = (const int4*)(ids + r*MM);   // 20 ids = 5 int4, broadcast
    const int4 i0 = __ldg(ip+0), i1 = __ldg(ip+1), i2 = __ldg(ip+2),
               i3 = __ldg(ip+3), i4 = __ldg(ip+4);
    const float4* e4 = (const float4*)emb;        // emb row = 32 float4

    float4 v[20];
    v[0]=__ldg(e4+i0.x*32+lane); v[1]=__ldg(e4+i0.y*32+lane);
    v[2]=__ldg(e4+i0.z*32+lane); v[3]=__ldg(e4+i0.w*32+lane);
    v[4]=__ldg(e4+i1.x*32+lane); v[5]=__ldg(e4+i1.y*32+lane);
    v[6]=__ldg(e4+i1.z*32+lane); v[7]=__ldg(e4+i1.w*32+lane);
    v[8]=__ldg(e4+i2.x*32+lane); v[9]=__ldg(e4+i2.y*32+lane);
    v[10]=__ldg(e4+i2.z*32+lane); v[11]=__ldg(e4+i2.w*32+lane);
    v[12]=__ldg(e4+i3.x*32+lane); v[13]=__ldg(e4+i3.y*32+lane);
    v[14]=__ldg(e4+i3.z*32+lane); v[15]=__ldg(e4+i3.w*32+lane);
    v[16]=__ldg(e4+i4.x*32+lane); v[17]=__ldg(e4+i4.y*32+lane);
    v[18]=__ldg(e4+i4.z*32+lane); v[19]=__ldg(e4+i4.w*32+lane);

    float4 a;
    a.x = (((v[0].x+v[1].x)+(v[2].x+v[3].x))+((v[4].x+v[5].x)+(v[6].x+v[7].x)))
        + (((v[8].x+v[9].x)+(v[10].x+v[11].x))+((v[12].x+v[13].x)+(v[14].x+v[15].x)))
        + ((v[16].x+v[17].x)+(v[18].x+v[19].x));
    a.y = (((v[0].y+v[1].y)+(v[2].y+v[3].y))+((v[4].y+v[5].y)+(v[6].y+v[7].y)))
        + (((v[8].y+v[9].y)+(v[10].y+v[11].y))+((v[12].y+v[13].y)+(v[14].y+v[15].y)))
        + ((v[16].y+v[17].y)+(v[18].y+v[19].y));
    a.z = (((v[0].z+v[1].z)+(v[2].z+v[3].z))+((v[4].z+v[5].z)+(v[6].z+v[7].z)))
        + (((v[8].z+v[9].z)+(v[10].z+v[11].z))+((v[12].z+v[13].z)+(v[14].z+v[15].z)))
        + ((v[16].z+v[17].z)+(v[18].z+v[19].z));
    a.w = (((v[0].w+v[1].w)+(v[2].w+v[3].w))+((v[4].w+v[5].w)+(v[6].w+v[7].w)))
        + (((v[8].w+v[9].w)+(v[10].w+v[11].w))+((v[12].w+v[13].w)+(v[14].w+v[15].w)))
        + ((v[16].w+v[17].w)+(v[18].w+v[19].w));

    const float inv = 1.0f / (float)__ldg(bsz + r);
    a.x *= inv; a.y *= inv; a.z *= inv; a.w *= inv;
    ((float4*)g_ub)[r*32 + lane] = a;
}

// ---------------------------------------------------------------------------
// K2: xg[row, j] = dot(W_ih[j,:], ub[row,:]) + b_ih[j]
// CTA i handles the batch PAIR (i, 255-i). Thread j owns W_ih row j in regs.
// ---------------------------------------------------------------------------
__global__ void __launch_bounds__(384,1) k_xg(const float* __restrict__ W_ih,
                                              const float* __restrict__ b_ih,
                                              const int*   __restrict__ lens){
    const int j = threadIdx.x;
    u64 w[64];
    const u64* wrow = (const u64*)(W_ih + j*EE);
    #pragma unroll
    for (int k = 0; k < 64; ++k) w[k] = wrow[k];
    const float bias = b_ih[j];

    const int b0 = blockIdx.x;
    const int b1 = (BB-1) - blockIdx.x;
    const int len0 = lens[b0], len1 = lens[b1];
    const int maxlen = max(len0, len1);

    __shared__ __align__(16) float su[2][2][EE];   // [buf][rowpair][e]

    const int rr = j >> 5, lane = j & 31;

    if (j < 64){                                   // preload t = 0 (len >= 1 always)
        const int bb = rr ? b1 : b0;
        ((float4*)su[0][rr])[lane] = ((const float4*)(g_ub + (bb*TT)*EE))[lane];
    }
    __syncthreads();

    for (int t = 0; t < maxlen; ++t){
        const int cur = t & 1, nxt = cur ^ 1;
        float4 pf; bool havepf = false;
        if (j < 64){
            const int bb = rr ? b1 : b0;
            const int ln = rr ? len1 : len0;
            if (t+1 < ln){
                pf = ((const float4*)(g_ub + (bb*TT + t+1)*EE))[lane];
                havepf = true;
            }
        }

        const bool a0 = (t < len0), a1 = (t < len1);
        if (a0 && a1){
            u64 c0a=0ull, c0b=0ull, c1a=0ull, c1b=0ull;
            const ulonglong2* h0p = (const ulonglong2*)su[cur][0];
            const ulonglong2* h1p = (const ulonglong2*)su[cur][1];
            #pragma unroll
            for (int k = 0; k < 32; ++k){
                ulonglong2 v0 = h0p[k], v1 = h1p[k];
                fma2(c0a, w[2*k  ], v0.x);
                fma2(c0b, w[2*k+1], v0.y);
                fma2(c1a, w[2*k  ], v1.x);
                fma2(c1b, w[2*k+1], v1.y);
            }
            g_xg[(b0*TT + t)*G3 + j] = hsum2(add2(c0a, c0b)) + bias;
            g_xg[(b1*TT + t)*G3 + j] = hsum2(add2(c1a, c1b)) + bias;
        } else {
            const ulonglong2* hp = (const ulonglong2*)su[cur][a0 ? 0 : 1];
            const int bb = a0 ? b0 : b1;
            u64 ca=0ull, cb=0ull;
            #pragma unroll
            for (int k = 0; k < 32; ++k){
                ulonglong2 v = hp[k];
                fma2(ca, w[2*k  ], v.x);
                fma2(cb, w[2*k+1], v.y);
            }
            g_xg[(bb*TT + t)*G3 + j] = hsum2(add2(ca, cb)) + bias;
        }

        if (havepf)
            ((float4*)su[nxt][rr])[lane] = pf;
        __syncthreads();
    }
}

// ---------------------------------------------------------------------------
// K3: masked GRU scan. CTA i handles batch pair (i, 255-i).
// ---------------------------------------------------------------------------
__global__ void __launch_bounds__(384,1) k_scan(const float* __restrict__ W_hh,
                                                const float* __restrict__ b_hh,
                                                const float* __restrict__ h0,
                                                const int*   __restrict__ lens,
                                                float* __restrict__ out){
    const int j  = threadIdx.x;
    const int b0 = blockIdx.x;
    const int b1 = (BB-1) - blockIdx.x;

    u64 w[64];
    const u64* wrow = (const u64*)(W_hh + j*EE);
    #pragma unroll
    for (int k = 0; k < 64; ++k) w[k] = wrow[k];
    const float bias = b_hh[j];
    const int len0 = lens[b0], len1 = lens[b1];
    const int maxlen = max(len0, len1);

    __shared__ __align__(16) float sh[2][EE];     // hidden state
    __shared__ float srz[2][256];                 // r|z pre-activations
    __shared__ float shn[2][EE];                  // hn (recurrent n part)
    __shared__ float sxn[2][EE];                  // xn (input n part)

    if (j < 256){
        int row = j >> 7, e = j & 127;
        sh[row][e] = h0[(row ? b1 : b0)*EE + e];
    }
    __syncthreads();

    for (int t = 0; t < maxlen; ++t){
        const bool a0 = (t < len0), a1 = (t < len1);
        const float xg0 = a0 ? __ldg(&g_xg[(b0*TT + t)*G3 + j]) : 0.f;
        const float xg1 = a1 ? __ldg(&g_xg[(b1*TT + t)*G3 + j]) : 0.f;

        float hg0 = 0.f, hg1 = 0.f;
        if (a0 && a1){
            u64 c0a=0ull, c0b=0ull, c1a=0ull, c1b=0ull;
            const ulonglong2* h0p = (const ulonglong2*)sh[0];
            const ulonglong2* h1p = (const ulonglong2*)sh[1];
            #pragma unroll
            for (int k = 0; k < 32; ++k){
                ulonglong2 v0 = h0p[k], v1 = h1p[k];
                fma2(c0a, w[2*k  ], v0.x);
                fma2(c0b, w[2*k+1], v0.y);
                fma2(c1a, w[2*k  ], v1.x);
                fma2(c1b, w[2*k+1], v1.y);
            }
            hg0 = hsum2(add2(c0a, c0b)) + bias;
            hg1 = hsum2(add2(c1a, c1b)) + bias;
        } else {
            const ulonglong2* hp = (const ulonglong2*)sh[a0 ? 0 : 1];
            u64 ca=0ull, cb=0ull;
            #pragma unroll
            for (int k = 0; k < 32; ++k){
                ulonglong2 v = hp[k];
                fma2(ca, w[2*k  ], v.x);
                fma2(cb, w[2*k+1], v.y);
            }
            float hg = hsum2(add2(ca, cb)) + bias;
            if (a0) hg0 = hg; else hg1 = hg;
        }

        if (j < 256){
            srz[0][j] = hg0 + xg0;
            srz[1][j] = hg1 + xg1;
        } else {
            const int e = j - 256;
            shn[0][e] = hg0;  sxn[0][e] = xg0;
            shn[1][e] = hg1;  sxn[1][e] = xg1;
        }
        __syncthreads();

        if (j < 256){
            const int row = j >> 7, e = j & 127;
            const bool act = row ? a1 : a0;
            if (act){
                const float r  = sigf(srz[row][e]);
                const float z  = sigf(srz[row][e+128]);
                const float n  = tanhfast(sxn[row][e] + r * shn[row][e]);
                const float hp = sh[row][e];
                const float hv = (1.f - z) * n + z * hp;
                sh[row][e] = hv;
                out[((row ? b1 : b0)*TT + t)*EE + e] = hv;
            }
        }
        __syncthreads();
    }

    // zero-fill masked tail of dynamic_user (contiguous per batch row)
    {
        const float4 z4 = make_float4(0.f,0.f,0.f,0.f);
        float4* p0 = (float4*)(out + (b0*TT + len0)*EE);
        const int n0 = (TT - len0) * (EE/4);
        for (int k = j; k < n0; k += 384) p0[k] = z4;
        float4* p1 = (float4*)(out + (b1*TT + len1)*EE);
        const int n1 = (TT - len1) * (EE/4);
        for (int k = j; k < n1; k += 384) p1[k] = z4;
    }

    if (j < 256){
        const int row = j >> 7, e = j & 127;
        out[BB*TT*EE + (row ? b1 : b0)*EE + e] = sh[row][e];
    }
}

// ---------------------------------------------------------------------------
extern "C" void kernel_launch(void* const* d_in, const int* in_sizes, int n_in,
                              void* d_out, int out_size){
    const int*   item_ids = (const int*)  d_in[0];
    const int*   bsz      = (const int*)  d_in[1];
    const int*   lengths  = (const int*)  d_in[2];
    const float* emb      = (const float*)d_in[3];
    const float* W_ih     = (const float*)d_in[4];
    const float* W_hh     = (const float*)d_in[5];
    const float* b_ih     = (const float*)d_in[6];
    const float* b_hh     = (const float*)d_in[7];
    const float* h0       = (const float*)d_in[8];
    float* out = (float*)d_out;

    k_gather<<<1600, 256>>>(item_ids, bsz, lengths, emb);
    k_xg   <<<128, 384>>>(W_ih, b_ih, lengths);
    k_scan <<<128, 384>>>(W_hh, b_hh, h0, lengths, out);
}

// round 4
// speedup vs baseline: 1.0529x; 1.0529x over previous
#include <cuda_runtime.h>

#define BB 256
#define TT 50
#define MM 20
#define EE 128
#define G3 384

// scratch (no cudaMalloc allowed); .bss -> zeroed at module load.
// Slots for t >= len are NEVER written, so they stay 0 forever (deterministic).
__device__ __align__(16) float g_ub[BB*TT*EE];   // basket means   (B,T,E)
__device__ __align__(16) float g_xg[BB*TT*G3];   // input gates    (B,T,3E)

typedef unsigned long long u64;

__device__ __forceinline__ void fma2(u64 &acc, u64 a, u64 b){
    asm("fma.rn.f32x2 %0, %1, %2, %0;" : "+l"(acc) : "l"(a), "l"(b));
}
__device__ __forceinline__ u64 add2(u64 a, u64 b){
    u64 r; asm("add.rn.f32x2 %0, %1, %2;" : "=l"(r) : "l"(a), "l"(b));
    return r;
}
__device__ __forceinline__ float hsum2(u64 v){
    float lo, hi;
    asm("mov.b64 {%0,%1}, %2;" : "=f"(lo), "=f"(hi) : "l"(v));
    return lo + hi;
}
__device__ __forceinline__ float sigf(float x){
    return __fdividef(1.f, 1.f + __expf(-x));
}
__device__ __forceinline__ float tanhfast(float x){
    return __fdividef(2.f, 1.f + __expf(-2.f*x)) - 1.f;
}

// single-row dot: hg = dot(w_row_of_this_thread, srcbuf[0:128]) (+bias by caller)
__device__ __forceinline__ float dot_row(const u64* __restrict__ w,
                                         const float* __restrict__ src){
    u64 ca = 0ull, cb = 0ull;
    const ulonglong2* hp = (const ulonglong2*)src;
    #pragma unroll
    for (int k = 0; k < 32; ++k){
        ulonglong2 v = hp[k];
        fma2(ca, w[2*k  ], v.x);
        fma2(cb, w[2*k+1], v.y);
    }
    return hsum2(add2(ca, cb));
}

// ---------------------------------------------------------------------------
// K1: ub[b,t,:] = (1/basket) * sum_m emb[item_ids[b,t,m]]   (emb[0] == 0)
// One WARP per PAIR of rows (p, 12799-p) -> uniform work per warp.
// Lane covers one float4 chunk (32 lanes * 16B = 512B row).
// ---------------------------------------------------------------------------
__device__ __forceinline__ void gather_row(int r, int lane,
                                           const int* __restrict__ ids,
                                           const int* __restrict__ bsz,
                                           const int* __restrict__ lens,
                                           const float4* __restrict__ e4){
    const int b = r / TT;
    const int t = r - b*TT;
    if (t >= __ldg(lens + b)) return;             // uniform per warp

    const int4* ip = (const int4*)(ids + r*MM);   // 20 ids = 5 int4, broadcast
    const int4 i0 = __ldg(ip+0), i1 = __ldg(ip+1), i2 = __ldg(ip+2),
               i3 = __ldg(ip+3), i4 = __ldg(ip+4);

    float4 v[20];
    v[0]=__ldg(e4+i0.x*32+lane);  v[1]=__ldg(e4+i0.y*32+lane);
    v[2]=__ldg(e4+i0.z*32+lane);  v[3]=__ldg(e4+i0.w*32+lane);
    v[4]=__ldg(e4+i1.x*32+lane);  v[5]=__ldg(e4+i1.y*32+lane);
    v[6]=__ldg(e4+i1.z*32+lane);  v[7]=__ldg(e4+i1.w*32+lane);
    v[8]=__ldg(e4+i2.x*32+lane);  v[9]=__ldg(e4+i2.y*32+lane);
    v[10]=__ldg(e4+i2.z*32+lane); v[11]=__ldg(e4+i2.w*32+lane);
    v[12]=__ldg(e4+i3.x*32+lane); v[13]=__ldg(e4+i3.y*32+lane);
    v[14]=__ldg(e4+i3.z*32+lane); v[15]=__ldg(e4+i3.w*32+lane);
    v[16]=__ldg(e4+i4.x*32+lane); v[17]=__ldg(e4+i4.y*32+lane);
    v[18]=__ldg(e4+i4.z*32+lane); v[19]=__ldg(e4+i4.w*32+lane);

    float4 a;
    a.x = (((v[0].x+v[1].x)+(v[2].x+v[3].x))+((v[4].x+v[5].x)+(v[6].x+v[7].x)))
        + (((v[8].x+v[9].x)+(v[10].x+v[11].x))+((v[12].x+v[13].x)+(v[14].x+v[15].x)))
        + ((v[16].x+v[17].x)+(v[18].x+v[19].x));
    a.y = (((v[0].y+v[1].y)+(v[2].y+v[3].y))+((v[4].y+v[5].y)+(v[6].y+v[7].y)))
        + (((v[8].y+v[9].y)+(v[10].y+v[11].y))+((v[12].y+v[13].y)+(v[14].y+v[15].y)))
        + ((v[16].y+v[17].y)+(v[18].y+v[19].y));
    a.z = (((v[0].z+v[1].z)+(v[2].z+v[3].z))+((v[4].z+v[5].z)+(v[6].z+v[7].z)))
        + (((v[8].z+v[9].z)+(v[10].z+v[11].z))+((v[12].z+v[13].z)+(v[14].z+v[15].z)))
        + ((v[16].z+v[17].z)+(v[18].z+v[19].z));
    a.w = (((v[0].w+v[1].w)+(v[2].w+v[3].w))+((v[4].w+v[5].w)+(v[6].w+v[7].w)))
        + (((v[8].w+v[9].w)+(v[10].w+v[11].w))+((v[12].w+v[13].w)+(v[14].w+v[15].w)))
        + ((v[16].w+v[17].w)+(v[18].w+v[19].w));

    const float inv = 1.0f / (float)__ldg(bsz + r);
    a.x *= inv; a.y *= inv; a.z *= inv; a.w *= inv;
    ((float4*)g_ub)[r*32 + lane] = a;
}

__global__ void __launch_bounds__(256) k_gather(const int* __restrict__ ids,
                                                const int* __restrict__ bsz,
                                                const int* __restrict__ lens,
                                                const float* __restrict__ emb){
    const int p = blockIdx.x * 8 + (threadIdx.x >> 5);   // 0..6399
    const int lane = threadIdx.x & 31;
    const float4* e4 = (const float4*)emb;
    gather_row(p,            lane, ids, bsz, lens, e4);
    gather_row(12799 - p,    lane, ids, bsz, lens, e4);
}

// ---------------------------------------------------------------------------
// K2: xg[row, j] = dot(W_ih[j,:], ub[row,:]) + b_ih[j]
// CTA i handles the batch PAIR (i, 255-i). Thread j owns W_ih row j in regs.
// Per step: two conditional single-row dot loops (register-slack friendly).
// ---------------------------------------------------------------------------
__global__ void __launch_bounds__(384,1) k_xg(const float* __restrict__ W_ih,
                                              const float* __restrict__ b_ih,
                                              const int*   __restrict__ lens){
    const int j = threadIdx.x;
    u64 w[64];
    const u64* wrow = (const u64*)(W_ih + j*EE);
    #pragma unroll
    for (int k = 0; k < 64; ++k) w[k] = wrow[k];
    const float bias = b_ih[j];

    const int b0 = blockIdx.x;
    const int b1 = (BB-1) - blockIdx.x;
    const int len0 = lens[b0], len1 = lens[b1];
    const int maxlen = max(len0, len1);

    __shared__ __align__(16) float su[2][2][EE];   // [buf][rowpair][e]

    const int rr = j >> 5, lane = j & 31;

    if (j < 64){                                   // preload t = 0 (len >= 1 always)
        const int bb = rr ? b1 : b0;
        ((float4*)su[0][rr])[lane] = ((const float4*)(g_ub + (bb*TT)*EE))[lane];
    }
    __syncthreads();

    for (int t = 0; t < maxlen; ++t){
        const int cur = t & 1, nxt = cur ^ 1;
        float4 pf; bool havepf = false;
        if (j < 64){
            const int bb = rr ? b1 : b0;
            const int ln = rr ? len1 : len0;
            if (t+1 < ln){
                pf = ((const float4*)(g_ub + (bb*TT + t+1)*EE))[lane];
                havepf = true;
            }
        }

        if (t < len0)
            g_xg[(b0*TT + t)*G3 + j] = dot_row(w, su[cur][0]) + bias;
        if (t < len1)
            g_xg[(b1*TT + t)*G3 + j] = dot_row(w, su[cur][1]) + bias;

        if (havepf)
            ((float4*)su[nxt][rr])[lane] = pf;
        __syncthreads();
    }
}

// ---------------------------------------------------------------------------
// K3: masked GRU scan. CTA i handles batch pair (i, 255-i).
// Per step: two conditional single-row dot loops, then the gate phase.
// ---------------------------------------------------------------------------
__global__ void __launch_bounds__(384,1) k_scan(const float* __restrict__ W_hh,
                                                const float* __restrict__ b_hh,
                                                const float* __restrict__ h0,
                                                const int*   __restrict__ lens,
                                                float* __restrict__ out){
    const int j  = threadIdx.x;
    const int b0 = blockIdx.x;
    const int b1 = (BB-1) - blockIdx.x;

    u64 w[64];
    const u64* wrow = (const u64*)(W_hh + j*EE);
    #pragma unroll
    for (int k = 0; k < 64; ++k) w[k] = wrow[k];
    const float bias = b_hh[j];
    const int len0 = lens[b0], len1 = lens[b1];
    const int maxlen = max(len0, len1);

    __shared__ __align__(16) float sh[2][EE];     // hidden state
    __shared__ float srz[2][256];                 // r|z pre-activations
    __shared__ float shn[2][EE];                  // hn (recurrent n part)
    __shared__ float sxn[2][EE];                  // xn (input n part)

    if (j < 256){
        int row = j >> 7, e = j & 127;
        sh[row][e] = h0[(row ? b1 : b0)*EE + e];
    }
    __syncthreads();

    for (int t = 0; t < maxlen; ++t){
        const bool a0 = (t < len0), a1 = (t < len1);
        float xg0 = 0.f, xg1 = 0.f;
        if (a0) xg0 = __ldg(&g_xg[(b0*TT + t)*G3 + j]);
        if (a1) xg1 = __ldg(&g_xg[(b1*TT + t)*G3 + j]);

        float hg0 = 0.f, hg1 = 0.f;
        if (a0) hg0 = dot_row(w, sh[0]) + bias;
        if (a1) hg1 = dot_row(w, sh[1]) + bias;

        if (j < 256){
            srz[0][j] = hg0 + xg0;
            srz[1][j] = hg1 + xg1;
        } else {
            const int e = j - 256;
            shn[0][e] = hg0;  sxn[0][e] = xg0;
            shn[1][e] = hg1;  sxn[1][e] = xg1;
        }
        __syncthreads();

        if (j < 256){
            const int row = j >> 7, e = j & 127;
            const bool act = row ? a1 : a0;
            if (act){
                const float r  = sigf(srz[row][e]);
                const float z  = sigf(srz[row][e+128]);
                const float n  = tanhfast(sxn[row][e] + r * shn[row][e]);
                const float hp = sh[row][e];
                const float hv = (1.f - z) * n + z * hp;
                sh[row][e] = hv;
                out[((row ? b1 : b0)*TT + t)*EE + e] = hv;
            }
        }
        __syncthreads();
    }

    // zero-fill masked tail of dynamic_user (contiguous per batch row)
    {
        const float4 z4 = make_float4(0.f,0.f,0.f,0.f);
        float4* p0 = (float4*)(out + (b0*TT + len0)*EE);
        const int n0 = (TT - len0) * (EE/4);
        for (int k = j; k < n0; k += 384) p0[k] = z4;
        float4* p1 = (float4*)(out + (b1*TT + len1)*EE);
        const int n1 = (TT - len1) * (EE/4);
        for (int k = j; k < n1; k += 384) p1[k] = z4;
    }

    if (j < 256){
        const int row = j >> 7, e = j & 127;
        out[BB*TT*EE + (row ? b1 : b0)*EE + e] = sh[row][e];
    }
}

// ---------------------------------------------------------------------------
extern "C" void kernel_launch(void* const* d_in, const int* in_sizes, int n_in,
                              void* d_out, int out_size){
    const int*   item_ids = (const int*)  d_in[0];
    const int*   bsz      = (const int*)  d_in[1];
    const int*   lengths  = (const int*)  d_in[2];
    const float* emb      = (const float*)d_in[3];
    const float* W_ih     = (const float*)d_in[4];
    const float* W_hh     = (const float*)d_in[5];
    const float* b_ih     = (const float*)d_in[6];
    const float* b_hh     = (const float*)d_in[7];
    const float* h0       = (const float*)d_in[8];
    float* out = (float*)d_out;

    k_gather<<<800, 256>>>(item_ids, bsz, lengths, emb);
    k_xg   <<<128, 384>>>(W_ih, b_ih, lengths);
    k_scan <<<128, 384>>>(W_hh, b_hh, h0, lengths, out);
}